// round 2
// baseline (speedup 1.0000x reference)
#include <cuda_runtime.h>

// ---------------- problem constants ----------------
#define NBLK   6
#define DF     45          // features
#define HID    256         // hidden width
#define LHID   2           // hidden layers per block
#define MPAR   23          // params per feature (3K-1, K=8)
#define DM     (DF*MPAR)   // 1035
#define ROWS   64          // batch rows per CTA
#define NTHR   256
#define FPG    9           // features per spline group (45 = 5*9)
#define PCOLS  (FPG*MPAR)  // 207
#define FGCNT  5
#define K0PAD  48          // layer-0 K padded (45 feat + cond + 2 zero)

// ---------------- scratch (masked / transposed weights) ----------------
__device__ float g_W0t[NBLK * K0PAD * HID];          // [b][k][h]
__device__ float g_b0c[NBLK * HID];
__device__ float g_Wht[NBLK * LHID * HID * HID];     // [b][l][k][o]
__device__ float g_Wft[NBLK * HID * DM];             // [b][k][o]

// ---------------- prep kernels (apply MADE masks, transpose) ----------------
__global__ void prep_w0(const float* __restrict__ W0, const float* __restrict__ Wc,
                        const float* __restrict__ b0, const float* __restrict__ bc) {
    int idx = blockIdx.x * blockDim.x + threadIdx.x;
    const int total = NBLK * K0PAD * HID;
    if (idx < total) {
        int b = idx / (K0PAD * HID);
        int rem = idx % (K0PAD * HID);
        int k = rem / HID;
        int h = rem % HID;
        float v = 0.0f;
        if (k < DF) {                 // m0[h][d] = (h%44 >= d)
            v = ((h % 44) >= k) ? W0[(b * HID + h) * DF + k] : 0.0f;
        } else if (k == DF) {         // cond weight (unmasked)
            v = Wc[b * HID + h];
        }
        g_W0t[idx] = v;
    }
    if (idx < NBLK * HID) g_b0c[idx] = b0[idx] + bc[idx];
}

__global__ void prep_wh(const float* __restrict__ Wh) {
    int idx = blockIdx.x * blockDim.x + threadIdx.x;
    const int total = NBLK * LHID * HID * HID;
    if (idx >= total) return;
    int bl = idx >> 16;
    int k  = (idx >> 8) & 255;
    int o  = idx & 255;
    // mh[o][k] = (o%44 >= k%44)
    float v = ((o % 44) >= (k % 44)) ? Wh[(bl * HID + o) * HID + k] : 0.0f;
    g_Wht[idx] = v;
}

__global__ void prep_wf(const float* __restrict__ Wf) {
    int idx = blockIdx.x * blockDim.x + threadIdx.x;
    const int total = NBLK * HID * DM;
    if (idx >= total) return;
    int b = idx / (HID * DM);
    int rem = idx % (HID * DM);
    int k = rem / DM;
    int o = rem % DM;
    // mf[o][k] = (feature(o) > k%44), feature = o/23
    float v = ((o / MPAR) > (k % 44)) ? Wf[(b * DM + o) * HID + k] : 0.0f;
    g_Wft[idx] = v;
}

// ---------------- fused GEMM tile: [64 rows] x [NJ*32 cols], K-loop, weights staged in smem ----------------
// src: smem [64][SSTR]; Wt: global [.. K ..][LDW] (already col-offset); dst: smem [64][DSTR]
template<int NJ, int SSTR, int K, int NCOLS, int LDW, int DSTR, bool RELU>
__device__ __forceinline__ void gemm_tile(const float* __restrict__ Wt,
                                          const float* __restrict__ bias,
                                          const float* __restrict__ src,
                                          float* __restrict__ dst,
                                          float* __restrict__ Wsm, int tid)
{
    const int rg = tid >> 5;      // 0..7 row group (8 rows each)
    const int cg = tid & 31;      // lane -> col within group
    float acc[8][NJ];
    #pragma unroll
    for (int j = 0; j < NJ; j++) {
        int c = cg + 32 * j;
        float bv = (c < NCOLS) ? bias[c] : 0.0f;
        #pragma unroll
        for (int i = 0; i < 8; i++) acc[i][j] = bv;
    }
    const float* srcb = src + rg * 8 * SSTR;

    #pragma unroll 1
    for (int k0 = 0; k0 < K; k0 += 16) {
        __syncthreads();
        // stage 16 x NCOLS weight slab
        for (int idx = tid; idx < 16 * NCOLS; idx += NTHR) {
            int kk = idx / NCOLS;
            int c  = idx - kk * NCOLS;
            Wsm[kk * 256 + c] = Wt[(k0 + kk) * LDW + c];
        }
        __syncthreads();
        #pragma unroll
        for (int kk = 0; kk < 16; kk++) {
            float a[8];
            #pragma unroll
            for (int i = 0; i < 8; i++) a[i] = srcb[i * SSTR + k0 + kk];  // warp-broadcast
            #pragma unroll
            for (int j = 0; j < NJ; j++) {
                float w = Wsm[kk * 256 + cg + 32 * j];                    // conflict-free
                #pragma unroll
                for (int i = 0; i < 8; i++) acc[i][j] = fmaf(a[i], w, acc[i][j]);
            }
        }
    }
    // all threads have passed the last in-loop barrier together; safe to write dst (!= src)
    #pragma unroll
    for (int j = 0; j < NJ; j++) {
        int c = cg + 32 * j;
        if (c < NCOLS) {
            #pragma unroll
            for (int i = 0; i < 8; i++) {
                float v = acc[i][j];
                if (RELU) v = fmaxf(v, 0.0f);
                dst[(rg * 8 + i) * DSTR + c] = v;
            }
        }
    }
    __syncthreads();
}

// ---------------- rational-quadratic spline (tails='linear'), K=8 bins ----------------
__device__ __forceinline__ float2 rq_spline(const float* __restrict__ p, float x)
{
    const float TAIL = 13.815510557964274f;   // -log(1e-6)
    const float INVS = 0.0625f;               // 1/sqrt(256)
    bool inside = (x >= -TAIL) && (x <= TAIL);
    float xc = fminf(fmaxf(x, -TAIL), TAIL);

    float ew[8], eh[8];
    float mw = -1e30f, mhh = -1e30f;
    #pragma unroll
    for (int i = 0; i < 8; i++) {
        float a = p[i] * INVS, b = p[8 + i] * INVS;
        ew[i] = a; eh[i] = b;
        mw = fmaxf(mw, a); mhh = fmaxf(mhh, b);
    }
    float sw = 0.0f, sh = 0.0f;
    #pragma unroll
    for (int i = 0; i < 8; i++) {
        ew[i] = __expf(ew[i] - mw);  sw += ew[i];
        eh[i] = __expf(eh[i] - mhh); sh += eh[i];
    }
    float iw = 1.0f / sw, ihs = 1.0f / sh;

    float d[9];
    d[0] = 1.0f; d[8] = 1.0f;                 // MIN_D + softplus(const) == 1 exactly
    #pragma unroll
    for (int i = 0; i < 7; i++) {
        float u = p[16 + i];
        d[i + 1] = 1e-3f + fmaxf(u, 0.0f) + log1pf(__expf(-fabsf(u)));
    }

    // sequential scan over bins; predicated select of the containing bin
    float cumw = 0.0f, cumh = 0.0f;
    float cwl = -TAIL, chl = -TAIL;
    float bcwl = -TAIL, bw = 1.0f, bchl = -TAIL, bh2 = 1.0f, bd0 = 1.0f, bd1 = 1.0f;
    #pragma unroll
    for (int i = 0; i < 8; i++) {
        cumw += 1e-3f + 0.992f * (ew[i] * iw);
        cumh += 1e-3f + 0.992f * (eh[i] * ihs);
        float cwr = (i == 7) ? TAIL : fmaf(2.0f * TAIL, cumw, -TAIL);
        float chr = (i == 7) ? TAIL : fmaf(2.0f * TAIL, cumh, -TAIL);
        bool sel = (xc >= cwl);
        if (sel) { bcwl = cwl; bw = cwr - cwl; bchl = chl; bh2 = chr - chl; bd0 = d[i]; bd1 = d[i + 1]; }
        cwl = cwr; chl = chr;
    }

    float th    = (xc - bcwl) / bw;
    float th1   = th * (1.0f - th);
    float delta = bh2 / bw;
    float den   = delta + (bd0 + bd1 - 2.0f * delta) * th1;
    float y     = bchl + bh2 * (delta * th * th + bd0 * th1) / den;
    float omt   = 1.0f - th;
    float lnum  = delta * delta * (bd1 * th * th + 2.0f * delta * th1 + bd0 * omt * omt);
    float lad   = __logf(lnum) - 2.0f * __logf(den);

    float2 r;
    r.x = inside ? y : x;
    r.y = inside ? lad : 0.0f;
    return r;
}

// ---------------- main fused kernel ----------------
#define SMEM_FLOATS (ROWS*48 + ROWS*256 + ROWS*256 + 16*256 + ROWS)
#define SMEM_BYTES  (SMEM_FLOATS * 4)

__global__ __launch_bounds__(NTHR, 1)
void maf_kernel(const float* __restrict__ x, const float* __restrict__ cond,
                const float* __restrict__ bh, const float* __restrict__ bf,
                float* __restrict__ out)
{
    extern __shared__ float sm[];
    float* z_s  = sm;                       // [64][48]: f0..44 = z, 45 = cond, 46/47 = 0
    float* hidA = z_s + ROWS * 48;          // [64][256]
    float* hidB = hidA + ROWS * 256;        // [64][256], aliased as params [64][207]
    float* Wsm  = hidB + ROWS * 256;        // [16][256]
    float* ld_s = Wsm + 16 * 256;           // [64]

    const int tid  = threadIdx.x;
    const int row0 = blockIdx.x * ROWS;

    for (int idx = tid; idx < ROWS * DF; idx += NTHR) {
        int r = idx / DF, f = idx - r * DF;
        z_s[r * 48 + f] = x[(row0 + r) * DF + f];
    }
    if (tid < ROWS) {
        z_s[tid * 48 + 45] = cond[row0 + tid];
        z_s[tid * 48 + 46] = 0.0f;
        z_s[tid * 48 + 47] = 0.0f;
        ld_s[tid] = 0.0f;
    }
    // first gemm's internal barrier orders these writes before any read

    for (int b = 0; b < NBLK; b++) {
        // layer 0 (z + cond -> hid), no relu
        gemm_tile<8, 48, K0PAD, 256, 256, 256, false>(
            g_W0t + b * K0PAD * HID, g_b0c + b * HID, z_s, hidA, Wsm, tid);
        // hidden layers with relu
        gemm_tile<8, 256, 256, 256, 256, 256, true>(
            g_Wht + (b * 2 + 0) * HID * HID, bh + (b * 2 + 0) * HID, hidA, hidB, Wsm, tid);
        gemm_tile<8, 256, 256, 256, 256, 256, true>(
            g_Wht + (b * 2 + 1) * HID * HID, bh + (b * 2 + 1) * HID, hidB, hidA, Wsm, tid);
        // output layer + spline, 5 feature groups of 9
        for (int fg = 0; fg < FGCNT; fg++) {
            const int colbase = fg * PCOLS;
            gemm_tile<7, 256, 256, PCOLS, DM, PCOLS, false>(
                g_Wft + b * HID * DM + colbase, bf + b * DM + colbase, hidA, hidB, Wsm, tid);
            for (int t = tid; t < ROWS * FPG; t += NTHR) {
                int r  = t & 63;
                int fl = t >> 6;
                int f  = fg * FPG + fl;
                float xv = z_s[r * 48 + f];
                float2 yr = rq_spline(&hidB[r * PCOLS + fl * MPAR], xv);
                z_s[r * 48 + f] = yr.x;
                atomicAdd(&ld_s[r], yr.y);
            }
            __syncthreads();
        }
    }
    __syncthreads();
    if (tid < ROWS) {
        float s = 0.0f;
        #pragma unroll
        for (int f = 0; f < DF; f++) { float v = z_s[tid * 48 + f]; s = fmaf(v, v, s); }
        out[row0 + tid] = -0.5f * s - 41.35223399420827f + ld_s[tid];
    }
}

// ---------------- launch ----------------
extern "C" void kernel_launch(void* const* d_in, const int* in_sizes, int n_in,
                              void* d_out, int out_size) {
    const float* x    = (const float*)d_in[0];
    const float* cond = (const float*)d_in[1];
    const float* W0   = (const float*)d_in[2];
    const float* b0   = (const float*)d_in[3];
    const float* Wc   = (const float*)d_in[4];
    const float* bc   = (const float*)d_in[5];
    const float* Wh   = (const float*)d_in[6];
    const float* bh   = (const float*)d_in[7];
    const float* Wf   = (const float*)d_in[8];
    const float* bf   = (const float*)d_in[9];
    float* out = (float*)d_out;
    const int B = in_sizes[0] / DF;

    prep_w0<<<(NBLK * K0PAD * HID + 255) / 256, 256>>>(W0, Wc, b0, bc);
    prep_wh<<<(NBLK * LHID * HID * HID + 255) / 256, 256>>>(Wh);
    prep_wf<<<(NBLK * HID * DM + 255) / 256, 256>>>(Wf);

    cudaFuncSetAttribute(maf_kernel, cudaFuncAttributeMaxDynamicSharedMemorySize, SMEM_BYTES);
    maf_kernel<<<B / ROWS, NTHR, SMEM_BYTES>>>(x, cond, bh, bf, out);
}